// round 2
// baseline (speedup 1.0000x reference)
#include <cuda_runtime.h>
#include <math.h>

#define B_   128
#define T_   512
#define C_   384
#define NH_  6
#define HD_  64
#define RD_  16
#define TC3  1152   // 3*C
#define BT   (B_*T_)            // 65536

// ---------------- scratch (static device globals; no allocation) -------------
__device__ float g_qkv[(size_t)BT * TC3];          // 75.5M floats
__device__ float g_q[(size_t)B_ * NH_ * T_ * HD_]; // 25.2M
__device__ float g_k[(size_t)B_ * NH_ * T_ * HD_];
__device__ float g_v[(size_t)B_ * NH_ * T_ * HD_];
__device__ float g_o[(size_t)BT * C_];             // 25.2M

// =============================================================================
// SGEMM, NT layout: C[m,n] = sum_k A[m*K+k] * B[n*K+k]
// BM=BN=128, BK=16, 256 threads, 8x8 per-thread tile.
// Requires M%128==0, N%128==0, K%16==0 (true for all uses here).
// =============================================================================
__global__ __launch_bounds__(256) void sgemm_nt(
    const float* __restrict__ A, const float* __restrict__ Bm,
    float* __restrict__ Cc, int M, int N, int K)
{
    const int BM = 128, BN = 128, BK = 16;
    __shared__ float As[BK][BM + 4];
    __shared__ float Bs[BK][BN + 4];

    const int tid = threadIdx.x;
    const int tx = tid & 15;      // n dim
    const int ty = tid >> 4;      // m dim
    const int bm = blockIdx.y * BM;
    const int bn = blockIdx.x * BN;

    const int lrow = tid >> 2;    // 0..63
    const int lc4  = tid & 3;     // 0..3  (float4 along K)

    const float* Ag = A  + (size_t)bm * K;
    const float* Bg = Bm + (size_t)bn * K;

    float acc[8][8];
#pragma unroll
    for (int i = 0; i < 8; i++)
#pragma unroll
        for (int j = 0; j < 8; j++) acc[i][j] = 0.0f;

    for (int kk = 0; kk < K; kk += BK) {
#pragma unroll
        for (int p = 0; p < 2; p++) {
            int r = lrow + p * 64;
            float4 av = *(const float4*)(Ag + (size_t)r * K + kk + lc4 * 4);
            As[lc4 * 4 + 0][r] = av.x;
            As[lc4 * 4 + 1][r] = av.y;
            As[lc4 * 4 + 2][r] = av.z;
            As[lc4 * 4 + 3][r] = av.w;
            float4 bv = *(const float4*)(Bg + (size_t)r * K + kk + lc4 * 4);
            Bs[lc4 * 4 + 0][r] = bv.x;
            Bs[lc4 * 4 + 1][r] = bv.y;
            Bs[lc4 * 4 + 2][r] = bv.z;
            Bs[lc4 * 4 + 3][r] = bv.w;
        }
        __syncthreads();

#pragma unroll
        for (int k = 0; k < BK; k++) {
            float ra[8], rb[8];
            *(float4*)(ra)     = *(const float4*)&As[k][ty * 8];
            *(float4*)(ra + 4) = *(const float4*)&As[k][ty * 8 + 4];
            *(float4*)(rb)     = *(const float4*)&Bs[k][tx * 8];
            *(float4*)(rb + 4) = *(const float4*)&Bs[k][tx * 8 + 4];
#pragma unroll
            for (int i = 0; i < 8; i++)
#pragma unroll
                for (int j = 0; j < 8; j++)
                    acc[i][j] = fmaf(ra[i], rb[j], acc[i][j]);
        }
        __syncthreads();
    }

#pragma unroll
    for (int i = 0; i < 8; i++) {
        float4 c0 = make_float4(acc[i][0], acc[i][1], acc[i][2], acc[i][3]);
        float4 c1 = make_float4(acc[i][4], acc[i][5], acc[i][6], acc[i][7]);
        float* crow = Cc + (size_t)(bm + ty * 8 + i) * N + bn + tx * 8;
        *(float4*)(crow)     = c0;
        *(float4*)(crow + 4) = c1;
    }
}

// =============================================================================
// RoPE + scatter: qkv[B,T,1152] -> q/k/v [B,NH,T,HD]; rope on first 16 dims of
// q and k; q additionally pre-scaled by 1/sqrt(HD)=0.125.
// One thread per element of the 3 output arrays (75.5M threads).
// =============================================================================
__global__ __launch_bounds__(256) void rope_scatter(
    const float* __restrict__ qkv, const float* __restrict__ cosb,
    const float* __restrict__ sinb,
    float* __restrict__ q, float* __restrict__ k, float* __restrict__ v)
{
    unsigned idx = blockIdx.x * 256u + threadIdx.x;
    // decompose: [w][b][h][t][hd]
    int hd = idx & 63;
    unsigned r = idx >> 6;
    int t = r & 511; r >>= 9;
    int h = r % NH_; r /= NH_;
    int b = r % B_;
    int w = r / B_;            // 0=q,1=k,2=v

    const float* src = qkv + ((size_t)(b * T_ + t)) * TC3 + w * C_ + h * HD_;

    float val;
    if (w == 2 || hd >= RD_) {
        val = src[hd];
    } else if (hd < RD_ / 2) {
        float c = cosb[t * 8 + hd], s = sinb[t * 8 + hd];
        val = src[hd] * c - src[hd + 8] * s;
    } else {
        int p = hd - 8;
        float c = cosb[t * 8 + p], s = sinb[t * 8 + p];
        val = src[hd] * c + src[hd - 8] * s;
    }
    if (w == 0) val *= 0.125f;   // 1/sqrt(64) folded into Q

    size_t rest = (((size_t)(b * NH_ + h) * T_ + t) * HD_ + hd);
    float* outp = (w == 0) ? q : (w == 1) ? k : v;
    outp[rest] = val;
}

// =============================================================================
// Flash-style causal attention. Grid: (T/64, B*NH). 256 threads/CTA.
// Q pre-scaled. Q,K,V: [B*NH, T, 64]. Output written as o[B,T,C] (head-fused).
// smem: Qs[64][65], Ks[64][65], Ps[64][65], Vs[64][64]  = 66304 B (dynamic)
// =============================================================================
__global__ __launch_bounds__(256) void attn_kernel(
    const float* __restrict__ Qg, const float* __restrict__ Kg,
    const float* __restrict__ Vg, float* __restrict__ Og)
{
    extern __shared__ float sm[];
    float* Qs = sm;                    // 64*65
    float* Ks = Qs + 64 * 65;          // 64*65
    float* Ps = Ks + 64 * 65;          // 64*65
    float* Vs = Ps + 64 * 65;          // 64*64

    const int tid = threadIdx.x;
    const int tx = tid & 15;           // key-col / hd-col group
    const int ty = tid >> 4;           // query-row group
    const int qt = blockIdx.x;
    const int bh = blockIdx.y;

    const float* qg = Qg + ((size_t)bh * T_ + qt * 64) * HD_;

    // load Q tile (already scaled)
#pragma unroll
    for (int p = 0; p < 4; p++) {
        int i4 = p * 256 + tid;        // float4 index 0..1023
        int row = i4 >> 4, c4 = i4 & 15;
        float4 qv = *(const float4*)(qg + row * 64 + c4 * 4);
        float* d = &Qs[row * 65 + c4 * 4];
        d[0] = qv.x; d[1] = qv.y; d[2] = qv.z; d[3] = qv.w;
    }

    float m_i[4], l_i[4], acc[4][4];
#pragma unroll
    for (int i = 0; i < 4; i++) {
        m_i[i] = -1e30f; l_i[i] = 0.0f;
#pragma unroll
        for (int j = 0; j < 4; j++) acc[i][j] = 0.0f;
    }

    for (int kt = 0; kt <= qt; kt++) {
        __syncthreads();   // protect Ks/Vs/Ps from previous iteration readers
        const float* kg = Kg + ((size_t)bh * T_ + kt * 64) * HD_;
        const float* vg = Vg + ((size_t)bh * T_ + kt * 64) * HD_;
#pragma unroll
        for (int p = 0; p < 4; p++) {
            int i4 = p * 256 + tid;
            int row = i4 >> 4, c4 = i4 & 15;
            float4 kv = *(const float4*)(kg + row * 64 + c4 * 4);
            float* d = &Ks[row * 65 + c4 * 4];
            d[0] = kv.x; d[1] = kv.y; d[2] = kv.z; d[3] = kv.w;
            float4 vv = *(const float4*)(vg + row * 64 + c4 * 4);
            *(float4*)&Vs[row * 64 + c4 * 4] = vv;
        }
        __syncthreads();

        // S = Q K^T (64x64 tile, 4x4 per thread)
        float s[4][4];
#pragma unroll
        for (int i = 0; i < 4; i++)
#pragma unroll
            for (int j = 0; j < 4; j++) s[i][j] = 0.0f;

#pragma unroll 8
        for (int d = 0; d < 64; d++) {
            float qv[4], kv[4];
#pragma unroll
            for (int i = 0; i < 4; i++) qv[i] = Qs[(ty * 4 + i) * 65 + d];
#pragma unroll
            for (int j = 0; j < 4; j++) kv[j] = Ks[(tx * 4 + j) * 65 + d];
#pragma unroll
            for (int i = 0; i < 4; i++)
#pragma unroll
                for (int j = 0; j < 4; j++)
                    s[i][j] = fmaf(qv[i], kv[j], s[i][j]);
        }

        if (kt == qt) {
#pragma unroll
            for (int i = 0; i < 4; i++)
#pragma unroll
                for (int j = 0; j < 4; j++)
                    if (tx * 4 + j > ty * 4 + i) s[i][j] = -1e30f;
        }

        // online softmax update
#pragma unroll
        for (int i = 0; i < 4; i++) {
            float rmax = fmaxf(fmaxf(s[i][0], s[i][1]), fmaxf(s[i][2], s[i][3]));
#pragma unroll
            for (int off = 8; off >= 1; off >>= 1)
                rmax = fmaxf(rmax, __shfl_xor_sync(0xffffffffu, rmax, off));
            float mnew = fmaxf(m_i[i], rmax);
            float corr = __expf(m_i[i] - mnew);
            m_i[i] = mnew;
            float rs = 0.0f;
#pragma unroll
            for (int j = 0; j < 4; j++) {
                s[i][j] = __expf(s[i][j] - mnew);
                rs += s[i][j];
            }
#pragma unroll
            for (int off = 8; off >= 1; off >>= 1)
                rs += __shfl_xor_sync(0xffffffffu, rs, off);
            l_i[i] = l_i[i] * corr + rs;
#pragma unroll
            for (int j = 0; j < 4; j++) acc[i][j] *= corr;
            // stage P
            float* pr = &Ps[(ty * 4 + i) * 65 + tx * 4];
            pr[0] = s[i][0]; pr[1] = s[i][1]; pr[2] = s[i][2]; pr[3] = s[i][3];
        }
        __syncthreads();

        // O += P V  (inner over 64 keys)
#pragma unroll 8
        for (int kj = 0; kj < 64; kj++) {
            float pv[4];
#pragma unroll
            for (int i = 0; i < 4; i++) pv[i] = Ps[(ty * 4 + i) * 65 + kj];
            float4 vv = *(const float4*)&Vs[kj * 64 + tx * 4];
#pragma unroll
            for (int i = 0; i < 4; i++) {
                acc[i][0] = fmaf(pv[i], vv.x, acc[i][0]);
                acc[i][1] = fmaf(pv[i], vv.y, acc[i][1]);
                acc[i][2] = fmaf(pv[i], vv.z, acc[i][2]);
                acc[i][3] = fmaf(pv[i], vv.w, acc[i][3]);
            }
        }
    }

    // write O as [B, T, C] with head offset (fuses the transpose for out-proj)
    const int b = bh / NH_, h = bh % NH_;
#pragma unroll
    for (int i = 0; i < 4; i++) {
        float inv = 1.0f / l_i[i];
        float4 ov = make_float4(acc[i][0] * inv, acc[i][1] * inv,
                                acc[i][2] * inv, acc[i][3] * inv);
        size_t row = (size_t)b * T_ + qt * 64 + ty * 4 + i;
        *(float4*)(Og + row * C_ + h * HD_ + tx * 4) = ov;
    }
}

// =============================================================================
// launch
// =============================================================================
extern "C" void kernel_launch(void* const* d_in, const int* in_sizes, int n_in,
                              void* d_out, int out_size)
{
    const float* x    = (const float*)d_in[0];   // [128,512,384]
    const float* Wqkv = (const float*)d_in[1];   // [1152,384]
    const float* Wout = (const float*)d_in[2];   // [384,384]
    const float* cosb = (const float*)d_in[3];   // [1,1,512,8]
    const float* sinb = (const float*)d_in[4];   // [1,1,512,8]
    float* out = (float*)d_out;                  // [128,512,384]

    float *p_qkv, *p_q, *p_k, *p_v, *p_o;
    cudaGetSymbolAddress((void**)&p_qkv, g_qkv);
    cudaGetSymbolAddress((void**)&p_q,   g_q);
    cudaGetSymbolAddress((void**)&p_k,   g_k);
    cudaGetSymbolAddress((void**)&p_v,   g_v);
    cudaGetSymbolAddress((void**)&p_o,   g_o);

    // 1) QKV projection: [65536,1152] = x[65536,384] @ Wqkv^T
    {
        dim3 grid(TC3 / 128, BT / 128);
        sgemm_nt<<<grid, 256>>>(x, Wqkv, p_qkv, BT, TC3, C_);
    }

    // 2) RoPE + scatter to per-head layout (Q pre-scaled)
    {
        unsigned total = (unsigned)(3u * B_ * NH_ * T_ * HD_);
        rope_scatter<<<total / 256, 256>>>(p_qkv, cosb, sinb, p_q, p_k, p_v);
    }

    // 3) causal attention
    {
        int smem = (3 * 64 * 65 + 64 * 64) * (int)sizeof(float); // 66304
        cudaFuncSetAttribute(attn_kernel,
                             cudaFuncAttributeMaxDynamicSharedMemorySize, smem);
        dim3 grid(T_ / 64, B_ * NH_);
        attn_kernel<<<grid, 256, smem>>>(p_q, p_k, p_v, p_o);
    }

    // 4) output projection: [65536,384] = o[65536,384] @ Wout^T
    {
        dim3 grid(C_ / 128, BT / 128);
        sgemm_nt<<<grid, 256>>>(p_o, Wout, out, BT, C_, C_);
    }
}

// round 3
// speedup vs baseline: 1.0007x; 1.0007x over previous
#include <cuda_runtime.h>
#include <math.h>

#define B_   128
#define T_   512
#define C_   384
#define NH_  6
#define HD_  64
#define RD_  16
#define TC3  1152   // 3*C
#define BT   (B_*T_)            // 65536

// ---------------- scratch (static device globals; no allocation) -------------
__device__ float g_qkv[(size_t)BT * TC3];          // 75.5M floats
__device__ float g_q[(size_t)B_ * NH_ * T_ * HD_]; // 25.2M
__device__ float g_k[(size_t)B_ * NH_ * T_ * HD_];
__device__ float g_v[(size_t)B_ * NH_ * T_ * HD_];
__device__ float g_o[(size_t)BT * C_];             // 25.2M

// =============================================================================
// SGEMM, NT layout: C[m,n] = sum_k A[m*K+k] * B[n*K+k]
// BM=BN=128, BK=16, 256 threads, 8x8 per-thread tile.
// Requires M%128==0, N%128==0, K%16==0 (true for all uses here).
// =============================================================================
__global__ __launch_bounds__(256) void sgemm_nt(
    const float* __restrict__ A, const float* __restrict__ Bm,
    float* __restrict__ Cc, int M, int N, int K)
{
    const int BM = 128, BN = 128, BK = 16;
    __shared__ float As[BK][BM + 4];
    __shared__ float Bs[BK][BN + 4];

    const int tid = threadIdx.x;
    const int tx = tid & 15;      // n dim
    const int ty = tid >> 4;      // m dim
    const int bm = blockIdx.y * BM;
    const int bn = blockIdx.x * BN;

    const int lrow = tid >> 2;    // 0..63
    const int lc4  = tid & 3;     // 0..3  (float4 along K)

    const float* Ag = A  + (size_t)bm * K;
    const float* Bg = Bm + (size_t)bn * K;

    float acc[8][8];
#pragma unroll
    for (int i = 0; i < 8; i++)
#pragma unroll
        for (int j = 0; j < 8; j++) acc[i][j] = 0.0f;

    for (int kk = 0; kk < K; kk += BK) {
#pragma unroll
        for (int p = 0; p < 2; p++) {
            int r = lrow + p * 64;
            float4 av = *(const float4*)(Ag + (size_t)r * K + kk + lc4 * 4);
            As[lc4 * 4 + 0][r] = av.x;
            As[lc4 * 4 + 1][r] = av.y;
            As[lc4 * 4 + 2][r] = av.z;
            As[lc4 * 4 + 3][r] = av.w;
            float4 bv = *(const float4*)(Bg + (size_t)r * K + kk + lc4 * 4);
            Bs[lc4 * 4 + 0][r] = bv.x;
            Bs[lc4 * 4 + 1][r] = bv.y;
            Bs[lc4 * 4 + 2][r] = bv.z;
            Bs[lc4 * 4 + 3][r] = bv.w;
        }
        __syncthreads();

#pragma unroll
        for (int k = 0; k < BK; k++) {
            float ra[8], rb[8];
            *(float4*)(ra)     = *(const float4*)&As[k][ty * 8];
            *(float4*)(ra + 4) = *(const float4*)&As[k][ty * 8 + 4];
            *(float4*)(rb)     = *(const float4*)&Bs[k][tx * 8];
            *(float4*)(rb + 4) = *(const float4*)&Bs[k][tx * 8 + 4];
#pragma unroll
            for (int i = 0; i < 8; i++)
#pragma unroll
                for (int j = 0; j < 8; j++)
                    acc[i][j] = fmaf(ra[i], rb[j], acc[i][j]);
        }
        __syncthreads();
    }

#pragma unroll
    for (int i = 0; i < 8; i++) {
        float4 c0 = make_float4(acc[i][0], acc[i][1], acc[i][2], acc[i][3]);
        float4 c1 = make_float4(acc[i][4], acc[i][5], acc[i][6], acc[i][7]);
        float* crow = Cc + (size_t)(bm + ty * 8 + i) * N + bn + tx * 8;
        *(float4*)(crow)     = c0;
        *(float4*)(crow + 4) = c1;
    }
}

// =============================================================================
// RoPE + scatter: qkv[B,T,1152] -> q/k/v [B,NH,T,HD]; rope on first 16 dims of
// q and k; q additionally pre-scaled by 1/sqrt(HD)=0.125.
// One thread per element of the 3 output arrays (75.5M threads).
// =============================================================================
__global__ __launch_bounds__(256) void rope_scatter(
    const float* __restrict__ qkv, const float* __restrict__ cosb,
    const float* __restrict__ sinb,
    float* __restrict__ q, float* __restrict__ k, float* __restrict__ v)
{
    unsigned idx = blockIdx.x * 256u + threadIdx.x;
    // decompose: [w][b][h][t][hd]
    int hd = idx & 63;
    unsigned r = idx >> 6;
    int t = r & 511; r >>= 9;
    int h = r % NH_; r /= NH_;
    int b = r % B_;
    int w = r / B_;            // 0=q,1=k,2=v

    const float* src = qkv + ((size_t)(b * T_ + t)) * TC3 + w * C_ + h * HD_;

    float val;
    if (w == 2 || hd >= RD_) {
        val = src[hd];
    } else if (hd < RD_ / 2) {
        float c = cosb[t * 8 + hd], s = sinb[t * 8 + hd];
        val = src[hd] * c - src[hd + 8] * s;
    } else {
        int p = hd - 8;
        float c = cosb[t * 8 + p], s = sinb[t * 8 + p];
        val = src[hd] * c + src[hd - 8] * s;
    }
    if (w == 0) val *= 0.125f;   // 1/sqrt(64) folded into Q

    size_t rest = (((size_t)(b * NH_ + h) * T_ + t) * HD_ + hd);
    float* outp = (w == 0) ? q : (w == 1) ? k : v;
    outp[rest] = val;
}

// =============================================================================
// Flash-style causal attention. Grid: (T/64, B*NH). 256 threads/CTA.
// Q pre-scaled. Q,K,V: [B*NH, T, 64]. Output written as o[B,T,C] (head-fused).
// smem: Qs[64][65], Ks[64][65], Ps[64][65], Vs[64][64]  = 66304 B (dynamic)
// =============================================================================
__global__ __launch_bounds__(256) void attn_kernel(
    const float* __restrict__ Qg, const float* __restrict__ Kg,
    const float* __restrict__ Vg, float* __restrict__ Og)
{
    extern __shared__ float sm[];
    float* Qs = sm;                    // 64*65
    float* Ks = Qs + 64 * 65;          // 64*65
    float* Ps = Ks + 64 * 65;          // 64*65
    float* Vs = Ps + 64 * 65;          // 64*64

    const int tid = threadIdx.x;
    const int tx = tid & 15;           // key-col / hd-col group
    const int ty = tid >> 4;           // query-row group
    const int qt = blockIdx.x;
    const int bh = blockIdx.y;

    const float* qg = Qg + ((size_t)bh * T_ + qt * 64) * HD_;

    // load Q tile (already scaled)
#pragma unroll
    for (int p = 0; p < 4; p++) {
        int i4 = p * 256 + tid;        // float4 index 0..1023
        int row = i4 >> 4, c4 = i4 & 15;
        float4 qv = *(const float4*)(qg + row * 64 + c4 * 4);
        float* d = &Qs[row * 65 + c4 * 4];
        d[0] = qv.x; d[1] = qv.y; d[2] = qv.z; d[3] = qv.w;
    }

    float m_i[4], l_i[4], acc[4][4];
#pragma unroll
    for (int i = 0; i < 4; i++) {
        m_i[i] = -1e30f; l_i[i] = 0.0f;
#pragma unroll
        for (int j = 0; j < 4; j++) acc[i][j] = 0.0f;
    }

    for (int kt = 0; kt <= qt; kt++) {
        __syncthreads();   // protect Ks/Vs/Ps from previous iteration readers
        const float* kg = Kg + ((size_t)bh * T_ + kt * 64) * HD_;
        const float* vg = Vg + ((size_t)bh * T_ + kt * 64) * HD_;
#pragma unroll
        for (int p = 0; p < 4; p++) {
            int i4 = p * 256 + tid;
            int row = i4 >> 4, c4 = i4 & 15;
            float4 kv = *(const float4*)(kg + row * 64 + c4 * 4);
            float* d = &Ks[row * 65 + c4 * 4];
            d[0] = kv.x; d[1] = kv.y; d[2] = kv.z; d[3] = kv.w;
            float4 vv = *(const float4*)(vg + row * 64 + c4 * 4);
            *(float4*)&Vs[row * 64 + c4 * 4] = vv;
        }
        __syncthreads();

        // S = Q K^T (64x64 tile, 4x4 per thread)
        float s[4][4];
#pragma unroll
        for (int i = 0; i < 4; i++)
#pragma unroll
            for (int j = 0; j < 4; j++) s[i][j] = 0.0f;

#pragma unroll 8
        for (int d = 0; d < 64; d++) {
            float qv[4], kv[4];
#pragma unroll
            for (int i = 0; i < 4; i++) qv[i] = Qs[(ty * 4 + i) * 65 + d];
#pragma unroll
            for (int j = 0; j < 4; j++) kv[j] = Ks[(tx * 4 + j) * 65 + d];
#pragma unroll
            for (int i = 0; i < 4; i++)
#pragma unroll
                for (int j = 0; j < 4; j++)
                    s[i][j] = fmaf(qv[i], kv[j], s[i][j]);
        }

        if (kt == qt) {
#pragma unroll
            for (int i = 0; i < 4; i++)
#pragma unroll
                for (int j = 0; j < 4; j++)
                    if (tx * 4 + j > ty * 4 + i) s[i][j] = -1e30f;
        }

        // online softmax update
#pragma unroll
        for (int i = 0; i < 4; i++) {
            float rmax = fmaxf(fmaxf(s[i][0], s[i][1]), fmaxf(s[i][2], s[i][3]));
#pragma unroll
            for (int off = 8; off >= 1; off >>= 1)
                rmax = fmaxf(rmax, __shfl_xor_sync(0xffffffffu, rmax, off));
            float mnew = fmaxf(m_i[i], rmax);
            float corr = __expf(m_i[i] - mnew);
            m_i[i] = mnew;
            float rs = 0.0f;
#pragma unroll
            for (int j = 0; j < 4; j++) {
                s[i][j] = __expf(s[i][j] - mnew);
                rs += s[i][j];
            }
#pragma unroll
            for (int off = 8; off >= 1; off >>= 1)
                rs += __shfl_xor_sync(0xffffffffu, rs, off);
            l_i[i] = l_i[i] * corr + rs;
#pragma unroll
            for (int j = 0; j < 4; j++) acc[i][j] *= corr;
            // stage P
            float* pr = &Ps[(ty * 4 + i) * 65 + tx * 4];
            pr[0] = s[i][0]; pr[1] = s[i][1]; pr[2] = s[i][2]; pr[3] = s[i][3];
        }
        __syncthreads();

        // O += P V  (inner over 64 keys)
#pragma unroll 8
        for (int kj = 0; kj < 64; kj++) {
            float pv[4];
#pragma unroll
            for (int i = 0; i < 4; i++) pv[i] = Ps[(ty * 4 + i) * 65 + kj];
            float4 vv = *(const float4*)&Vs[kj * 64 + tx * 4];
#pragma unroll
            for (int i = 0; i < 4; i++) {
                acc[i][0] = fmaf(pv[i], vv.x, acc[i][0]);
                acc[i][1] = fmaf(pv[i], vv.y, acc[i][1]);
                acc[i][2] = fmaf(pv[i], vv.z, acc[i][2]);
                acc[i][3] = fmaf(pv[i], vv.w, acc[i][3]);
            }
        }
    }

    // write O as [B, T, C] with head offset (fuses the transpose for out-proj)
    const int b = bh / NH_, h = bh % NH_;
#pragma unroll
    for (int i = 0; i < 4; i++) {
        float inv = 1.0f / l_i[i];
        float4 ov = make_float4(acc[i][0] * inv, acc[i][1] * inv,
                                acc[i][2] * inv, acc[i][3] * inv);
        size_t row = (size_t)b * T_ + qt * 64 + ty * 4 + i;
        *(float4*)(Og + row * C_ + h * HD_ + tx * 4) = ov;
    }
}

// =============================================================================
// launch
// =============================================================================
extern "C" void kernel_launch(void* const* d_in, const int* in_sizes, int n_in,
                              void* d_out, int out_size)
{
    const float* x    = (const float*)d_in[0];   // [128,512,384]
    const float* Wqkv = (const float*)d_in[1];   // [1152,384]
    const float* Wout = (const float*)d_in[2];   // [384,384]
    const float* cosb = (const float*)d_in[3];   // [1,1,512,8]
    const float* sinb = (const float*)d_in[4];   // [1,1,512,8]
    float* out = (float*)d_out;                  // [128,512,384]

    float *p_qkv, *p_q, *p_k, *p_v, *p_o;
    cudaGetSymbolAddress((void**)&p_qkv, g_qkv);
    cudaGetSymbolAddress((void**)&p_q,   g_q);
    cudaGetSymbolAddress((void**)&p_k,   g_k);
    cudaGetSymbolAddress((void**)&p_v,   g_v);
    cudaGetSymbolAddress((void**)&p_o,   g_o);

    // 1) QKV projection: [65536,1152] = x[65536,384] @ Wqkv^T
    {
        dim3 grid(TC3 / 128, BT / 128);
        sgemm_nt<<<grid, 256>>>(x, Wqkv, p_qkv, BT, TC3, C_);
    }

    // 2) RoPE + scatter to per-head layout (Q pre-scaled)
    {
        unsigned total = (unsigned)(3u * B_ * NH_ * T_ * HD_);
        rope_scatter<<<total / 256, 256>>>(p_qkv, cosb, sinb, p_q, p_k, p_v);
    }

    // 3) causal attention
    {
        int smem = (3 * 64 * 65 + 64 * 64) * (int)sizeof(float); // 66304
        cudaFuncSetAttribute(attn_kernel,
                             cudaFuncAttributeMaxDynamicSharedMemorySize, smem);
        dim3 grid(T_ / 64, B_ * NH_);
        attn_kernel<<<grid, 256, smem>>>(p_q, p_k, p_v, p_o);
    }

    // 4) output projection: [65536,384] = o[65536,384] @ Wout^T
    {
        dim3 grid(C_ / 128, BT / 128);
        sgemm_nt<<<grid, 256>>>(p_o, Wout, out, BT, C_, C_);
    }
}